// round 2
// baseline (speedup 1.0000x reference)
#include <cuda_runtime.h>

// Problem shape (fixed by the dataset instance)
#define BB   2
#define HH   32
#define SS   4096
#define DD   128
#define BLK  512
#define NB   (SS / BLK)          // 8
#define NCTA (BB * HH * NB)      // 512
#define NTHREADS 256
#define EPS_F 1e-6f

// Shared memory layout (floats)
#define SDM_OFF   0                       // 128x128 S_dm        (16384)
#define STAGE_OFF (SDM_OFF + DD * DD)     // staging: 64x128     (8192)
#define Z_OFF     (STAGE_OFF + 64 * DD)   // Z[128]
#define DEN_OFF   (Z_OFF + DD)            // den[64]
#define SMEM_FLOATS (DEN_OFF + 64)
#define SMEM_BYTES  (SMEM_FLOATS * 4)     // 99072 bytes

__device__ __forceinline__ float phi_elu1(float y) {
    // elu(y)+1 :  y>0 -> y+1 ;  y<=0 -> exp(y)
    return y > 0.0f ? y + 1.0f : __expf(y);
}

extern "C" __global__ void __launch_bounds__(NTHREADS, 2)
lin_attn_fused(const float* __restrict__ q,
               const float* __restrict__ k,
               const float* __restrict__ v,
               const float* __restrict__ sc,
               const float* __restrict__ bi,
               float* __restrict__ out)
{
    extern __shared__ float sm[];
    float* Sdm   = sm + SDM_OFF;
    float* stage = sm + STAGE_OFF;
    float* Zsm   = sm + Z_OFF;
    float* den   = sm + DEN_OFF;

    const int tid = threadIdx.x;
    const int tx  = tid & 15;   // 0..15 -> output cols (m)
    const int ty  = tid >> 4;   // 0..15 -> output rows (d / s)

    const int c  = blockIdx.x;
    const int n  = c % NB;
    const int bh = c / NB;
    const int h  = bh % HH;
    const long base = ((long)bh * SS + (long)n * BLK) * DD;

    const float* qb = q + base;
    const float* kb = k + base;
    const float* vb = v + base;
    float*       ob = out + base;

    // Loader-thread column (fixed across all staged chunks): d4 = (tid&31)*4
    const int c4 = (tid & 31) * 4;
    const float4 sc4 = *(const float4*)(sc + h * DD + c4);
    const float4 bi4 = *(const float4*)(bi + h * DD + c4);

    // ================= Phase 1: S_dm = phi(K)^T V ; Z = sum_s phi(K) ========
    float acc[8][8];
    #pragma unroll
    for (int i = 0; i < 8; ++i)
        #pragma unroll
        for (int j = 0; j < 8; ++j) acc[i][j] = 0.0f;

    float4 zacc = make_float4(0.f, 0.f, 0.f, 0.f);

    float* phik_s = stage;           // 16 x 128
    float* v_s    = stage + 16 * DD; // 16 x 128

    for (int ch = 0; ch < BLK / 16; ++ch) {
        const float* kc = kb + (long)ch * 16 * DD;
        const float* vc = vb + (long)ch * 16 * DD;
        #pragma unroll
        for (int t = 0; t < 2; ++t) {
            const int r = (tid >> 5) + t * 8;   // 0..15
            const float4 kv = *(const float4*)(kc + r * DD + c4);
            float4 p;
            p.x = phi_elu1(fmaf(kv.x, sc4.x, bi4.x));
            p.y = phi_elu1(fmaf(kv.y, sc4.y, bi4.y));
            p.z = phi_elu1(fmaf(kv.z, sc4.z, bi4.z));
            p.w = phi_elu1(fmaf(kv.w, sc4.w, bi4.w));
            *(float4*)(phik_s + r * DD + c4) = p;
            zacc.x += p.x; zacc.y += p.y; zacc.z += p.z; zacc.w += p.w;
            const float4 vv = *(const float4*)(vc + r * DD + c4);
            *(float4*)(v_s + r * DD + c4) = vv;
        }
        __syncthreads();
        #pragma unroll
        for (int r = 0; r < 16; ++r) {
            const float4 a0 = *(const float4*)(phik_s + r * DD + ty * 8);
            const float4 a1 = *(const float4*)(phik_s + r * DD + ty * 8 + 4);
            const float4 b0 = *(const float4*)(v_s    + r * DD + tx * 8);
            const float4 b1 = *(const float4*)(v_s    + r * DD + tx * 8 + 4);
            const float a[8] = {a0.x, a0.y, a0.z, a0.w, a1.x, a1.y, a1.z, a1.w};
            const float b[8] = {b0.x, b0.y, b0.z, b0.w, b1.x, b1.y, b1.z, b1.w};
            #pragma unroll
            for (int i = 0; i < 8; ++i)
                #pragma unroll
                for (int j = 0; j < 8; ++j)
                    acc[i][j] = fmaf(a[i], b[j], acc[i][j]);
        }
        __syncthreads();
    }

    // Dump S_dm to smem
    #pragma unroll
    for (int i = 0; i < 8; ++i) {
        float4 s0 = make_float4(acc[i][0], acc[i][1], acc[i][2], acc[i][3]);
        float4 s1 = make_float4(acc[i][4], acc[i][5], acc[i][6], acc[i][7]);
        *(float4*)(Sdm + (ty * 8 + i) * DD + tx * 8)     = s0;
        *(float4*)(Sdm + (ty * 8 + i) * DD + tx * 8 + 4) = s1;
    }

    // Reduce Z: 8 partials per d-column live across threads (tid>>5 = 0..7)
    *(float4*)(stage + (tid >> 5) * DD + c4) = zacc;
    __syncthreads();
    if (tid < DD) {
        float s = 0.0f;
        #pragma unroll
        for (int r = 0; r < 8; ++r) s += stage[r * DD + tid];
        Zsm[tid] = s;
    }
    __syncthreads();

    // ================= Phase 2: out = phi(Q) S_dm / (phi(Q).Z + eps) ========
    for (int ch = 0; ch < BLK / 64; ++ch) {
        const float* qc = qb + (long)ch * 64 * DD;
        // stage phi(Q) 64 rows
        #pragma unroll
        for (int t = 0; t < 8; ++t) {
            const int r = (tid >> 5) + t * 8;   // 0..63
            const float4 qv = *(const float4*)(qc + r * DD + c4);
            float4 p;
            p.x = phi_elu1(fmaf(qv.x, sc4.x, bi4.x));
            p.y = phi_elu1(fmaf(qv.y, sc4.y, bi4.y));
            p.z = phi_elu1(fmaf(qv.z, sc4.z, bi4.z));
            p.w = phi_elu1(fmaf(qv.w, sc4.w, bi4.w));
            *(float4*)(stage + r * DD + c4) = p;
        }
        __syncthreads();

        // den per row (64 rows; 64 threads each do a full 128-dot)
        if (tid < 64) {
            float s = 0.0f;
            #pragma unroll 8
            for (int d4 = 0; d4 < DD; d4 += 4) {
                const float4 a = *(const float4*)(stage + tid * DD + d4);
                const float4 z = *(const float4*)(Zsm + d4);
                s = fmaf(a.x, z.x, s);
                s = fmaf(a.y, z.y, s);
                s = fmaf(a.z, z.z, s);
                s = fmaf(a.w, z.w, s);
            }
            den[tid] = s + EPS_F;
        }
        __syncthreads();

        // GEMM: 64 rows x 128 cols ; thread tile 4 rows x 8 cols
        float acc2[4][8];
        #pragma unroll
        for (int i = 0; i < 4; ++i)
            #pragma unroll
            for (int j = 0; j < 8; ++j) acc2[i][j] = 0.0f;

        for (int d4 = 0; d4 < DD; d4 += 4) {
            float a4[4][4];
            #pragma unroll
            for (int i = 0; i < 4; ++i) {
                const float4 av = *(const float4*)(stage + (ty * 4 + i) * DD + d4);
                a4[i][0] = av.x; a4[i][1] = av.y; a4[i][2] = av.z; a4[i][3] = av.w;
            }
            #pragma unroll
            for (int dd = 0; dd < 4; ++dd) {
                const int d = d4 + dd;
                const float4 b0 = *(const float4*)(Sdm + d * DD + tx * 8);
                const float4 b1 = *(const float4*)(Sdm + d * DD + tx * 8 + 4);
                const float b[8] = {b0.x, b0.y, b0.z, b0.w, b1.x, b1.y, b1.z, b1.w};
                #pragma unroll
                for (int i = 0; i < 4; ++i)
                    #pragma unroll
                    for (int j = 0; j < 8; ++j)
                        acc2[i][j] = fmaf(a4[i][dd], b[j], acc2[i][j]);
            }
        }

        // scale by 1/den and store
        #pragma unroll
        for (int i = 0; i < 4; ++i) {
            const float inv = 1.0f / den[ty * 4 + i];
            float4 o0 = make_float4(acc2[i][0] * inv, acc2[i][1] * inv,
                                    acc2[i][2] * inv, acc2[i][3] * inv);
            float4 o1 = make_float4(acc2[i][4] * inv, acc2[i][5] * inv,
                                    acc2[i][6] * inv, acc2[i][7] * inv);
            const int row = ch * 64 + ty * 4 + i;
            *(float4*)(ob + (long)row * DD + tx * 8)     = o0;
            *(float4*)(ob + (long)row * DD + tx * 8 + 4) = o1;
        }
        __syncthreads();
    }
}

extern "C" void kernel_launch(void* const* d_in, const int* in_sizes, int n_in,
                              void* d_out, int out_size) {
    const float* q  = (const float*)d_in[0];
    const float* k  = (const float*)d_in[1];
    const float* v  = (const float*)d_in[2];
    const float* sc = (const float*)d_in[3];
    const float* bi = (const float*)d_in[4];
    float* out = (float*)d_out;

    cudaFuncSetAttribute(lin_attn_fused,
                         cudaFuncAttributeMaxDynamicSharedMemorySize, SMEM_BYTES);
    lin_attn_fused<<<NCTA, NTHREADS, SMEM_BYTES>>>(q, k, v, sc, bi, out);
}

// round 3
// speedup vs baseline: 2.8503x; 2.8503x over previous
#include <cuda_runtime.h>
#include <cstdint>

// Problem shape (fixed by the dataset instance)
#define BB   2
#define HH   32
#define SS   4096
#define DD   128
#define BLK  512
#define NB   (SS / BLK)          // 8
#define NCTA (BB * HH * NB)      // 512
#define NT   256
#define EPS_F 1e-6f

// Smem strides chosen for conflict-free mma fragment loads:
//  A-fragment loads (stride SPAD=132): bank = (4t + g) -> 32 distinct
//  B-fragment loads (stride VPAD=136): bank = (8t + g) -> 32 distinct
#define SPAD 132
#define VPAD 136

// Shared memory layout (floats)
#define SDM_OFF   0                        // S_dm: 128 x 136        (17408)
#define STAGE_OFF (DD * VPAD)              // stage: 64 x 132 region  (8448)
#define Z_OFF     (STAGE_OFF + 64 * SPAD)  // Z[128]
#define DEN_OFF   (Z_OFF + DD)             // den[64]
#define SMEM_FLOATS (DEN_OFF + 64)
#define SMEM_BYTES  (SMEM_FLOATS * 4)      // 104192 B -> 2 CTAs/SM

__device__ __forceinline__ float phi_elu1(float y) {
    return y > 0.0f ? y + 1.0f : __expf(y);
}

__device__ __forceinline__ uint32_t f2tf(float x) {
    uint32_t u;
    asm("cvt.rna.tf32.f32 %0, %1;" : "=r"(u) : "f"(x));
    return u;
}

__device__ __forceinline__ void mma_tf32(float* c, const uint32_t* a, const uint32_t* b) {
    asm volatile(
        "mma.sync.aligned.m16n8k8.row.col.f32.tf32.tf32.f32 "
        "{%0,%1,%2,%3}, {%4,%5,%6,%7}, {%8,%9}, {%0,%1,%2,%3};\n"
        : "+f"(c[0]), "+f"(c[1]), "+f"(c[2]), "+f"(c[3])
        : "r"(a[0]), "r"(a[1]), "r"(a[2]), "r"(a[3]), "r"(b[0]), "r"(b[1]));
}

extern "C" __global__ void __launch_bounds__(NT, 2)
lin_attn_tc(const float* __restrict__ q,
            const float* __restrict__ k,
            const float* __restrict__ v,
            const float* __restrict__ sc,
            const float* __restrict__ bi,
            float* __restrict__ out)
{
    extern __shared__ float sm[];
    float* Sdm   = sm + SDM_OFF;           // [128][VPAD]
    float* stage = sm + STAGE_OFF;         // phase1: phiK[16][SPAD] + V[16][VPAD]; phase2: phiQ[64][SPAD]
    float* Zsm   = sm + Z_OFF;             // [128]
    float* den   = sm + DEN_OFF;           // [64]

    float* phik_s = stage;                 // 16 x SPAD
    float* v_s    = stage + 16 * SPAD;     // 16 x VPAD

    const int tid  = threadIdx.x;
    const int lane = tid & 31;
    const int w    = tid >> 5;             // warp 0..7
    const int g    = lane >> 2;            // 0..7
    const int t    = lane & 3;             // 0..3

    const int c  = blockIdx.x;
    const int n  = c % NB;
    const int bh = c / NB;
    const int h  = bh % HH;
    const long base = ((long)bh * SS + (long)n * BLK) * DD;

    const float* qb = q + base;
    const float* kb = k + base;
    const float* vb = v + base;
    float*       ob = out + base;

    // loader mapping: fixed column group c4, rows (tid>>5)+8*j
    const int lrow = tid >> 5;             // 0..7
    const int c4   = (tid & 31) * 4;
    const float4 sc4 = *(const float4*)(sc + h * DD + c4);
    const float4 bi4 = *(const float4*)(bi + h * DD + c4);

    // ========== Phase 1: S_dm = phi(K)^T V  (128x128, K-dim 512), Z = sum phi(K)
    // warp tiling: wd in {0,1} covers 64 d-rows; wm in {0..3} covers 32 m-cols
    const int wd = w & 1;
    const int wm = w >> 1;

    float acc[4][4][4];
    #pragma unroll
    for (int a = 0; a < 4; ++a)
        #pragma unroll
        for (int b = 0; b < 4; ++b)
            #pragma unroll
            for (int r = 0; r < 4; ++r) acc[a][b][r] = 0.0f;

    float4 zacc = make_float4(0.f, 0.f, 0.f, 0.f);

    // prefetch chunk 0 (16 s-rows)
    float4 kv[2], vv[2];
    #pragma unroll
    for (int j = 0; j < 2; ++j) {
        const int r = lrow + 8 * j;
        kv[j] = *(const float4*)(kb + (long)r * DD + c4);
        vv[j] = *(const float4*)(vb + (long)r * DD + c4);
    }

    for (int ch = 0; ch < BLK / 16; ++ch) {
        // stage current chunk (phi(K) as tf32, V as tf32)
        #pragma unroll
        for (int j = 0; j < 2; ++j) {
            const int r = lrow + 8 * j;
            float4 p;
            p.x = phi_elu1(fmaf(kv[j].x, sc4.x, bi4.x));
            p.y = phi_elu1(fmaf(kv[j].y, sc4.y, bi4.y));
            p.z = phi_elu1(fmaf(kv[j].z, sc4.z, bi4.z));
            p.w = phi_elu1(fmaf(kv[j].w, sc4.w, bi4.w));
            zacc.x += p.x; zacc.y += p.y; zacc.z += p.z; zacc.w += p.w;
            uint4 pu = make_uint4(f2tf(p.x), f2tf(p.y), f2tf(p.z), f2tf(p.w));
            *(uint4*)(phik_s + r * SPAD + c4) = pu;
            uint4 vu = make_uint4(f2tf(vv[j].x), f2tf(vv[j].y), f2tf(vv[j].z), f2tf(vv[j].w));
            *(uint4*)(v_s + r * VPAD + c4) = vu;
        }
        __syncthreads();

        // prefetch next chunk (overlaps mma)
        if (ch < BLK / 16 - 1) {
            const float* kc = kb + (long)(ch + 1) * 16 * DD;
            const float* vc = vb + (long)(ch + 1) * 16 * DD;
            #pragma unroll
            for (int j = 0; j < 2; ++j) {
                const int r = lrow + 8 * j;
                kv[j] = *(const float4*)(kc + (long)r * DD + c4);
                vv[j] = *(const float4*)(vc + (long)r * DD + c4);
            }
        }

        // mma: 2 k-steps of 8 over the 16 staged s-rows
        #pragma unroll
        for (int ks = 0; ks < 2; ++ks) {
            const int sb = ks * 8;
            // B fragments (V), cached for all d-tiles
            uint32_t B[4][2];
            #pragma unroll
            for (int mt = 0; mt < 4; ++mt) {
                const int m = wm * 32 + mt * 8 + g;
                B[mt][0] = __float_as_uint(v_s[(sb + t) * VPAD + m]);
                B[mt][1] = __float_as_uint(v_s[(sb + t + 4) * VPAD + m]);
            }
            #pragma unroll
            for (int dt = 0; dt < 4; ++dt) {
                const int d0 = wd * 64 + dt * 16;
                uint32_t A[4];
                A[0] = __float_as_uint(phik_s[(sb + t)     * SPAD + d0 + g]);
                A[1] = __float_as_uint(phik_s[(sb + t)     * SPAD + d0 + g + 8]);
                A[2] = __float_as_uint(phik_s[(sb + t + 4) * SPAD + d0 + g]);
                A[3] = __float_as_uint(phik_s[(sb + t + 4) * SPAD + d0 + g + 8]);
                #pragma unroll
                for (int mt = 0; mt < 4; ++mt)
                    mma_tf32(acc[dt][mt], A, B[mt]);
            }
        }
        __syncthreads();
    }

    // write S_dm to smem
    #pragma unroll
    for (int dt = 0; dt < 4; ++dt) {
        const int d0 = wd * 64 + dt * 16;
        #pragma unroll
        for (int mt = 0; mt < 4; ++mt) {
            const int m = wm * 32 + mt * 8 + 2 * t;
            *(float2*)(Sdm + (d0 + g)     * VPAD + m) = make_float2(acc[dt][mt][0], acc[dt][mt][1]);
            *(float2*)(Sdm + (d0 + g + 8) * VPAD + m) = make_float2(acc[dt][mt][2], acc[dt][mt][3]);
        }
    }

    // reduce Z (zacc partials: 8 per column) -- reuse stage area
    *(float4*)(stage + lrow * DD + c4) = zacc;
    __syncthreads();
    if (tid < DD) {
        float s = 0.0f;
        #pragma unroll
        for (int r = 0; r < 8; ++r) s += stage[r * DD + tid];
        Zsm[tid] = s;
    }
    __syncthreads();

    // ========== Phase 2: out = phi(Q) S_dm / (phi(Q).Z + eps)
    // chunk = 64 s-rows; warp tiling: s0 = (w&3)*16, m0 = (w>>2)*64 (8 n-tiles)
    const int s0 = (w & 3) * 16;
    const int m0 = (w >> 2) * 64;

    // prefetch Q chunk 0
    float4 qreg[8];
    #pragma unroll
    for (int j = 0; j < 8; ++j) {
        const int r = lrow + 8 * j;
        qreg[j] = *(const float4*)(qb + (long)r * DD + c4);
    }

    for (int chq = 0; chq < BLK / 64; ++chq) {
        // stage phi(Q) as tf32
        #pragma unroll
        for (int j = 0; j < 8; ++j) {
            const int r = lrow + 8 * j;
            float4 p;
            p.x = phi_elu1(fmaf(qreg[j].x, sc4.x, bi4.x));
            p.y = phi_elu1(fmaf(qreg[j].y, sc4.y, bi4.y));
            p.z = phi_elu1(fmaf(qreg[j].z, sc4.z, bi4.z));
            p.w = phi_elu1(fmaf(qreg[j].w, sc4.w, bi4.w));
            uint4 pu = make_uint4(f2tf(p.x), f2tf(p.y), f2tf(p.z), f2tf(p.w));
            *(uint4*)(stage + r * SPAD + c4) = pu;
        }
        __syncthreads();

        // prefetch next Q chunk (overlaps den + mma)
        if (chq < BLK / 64 - 1) {
            const float* qc = qb + (long)(chq + 1) * 64 * DD;
            #pragma unroll
            for (int j = 0; j < 8; ++j) {
                const int r = lrow + 8 * j;
                qreg[j] = *(const float4*)(qc + (long)r * DD + c4);
            }
        }

        // den[row] = phiQ(row) . Z + eps  (4 lanes per row, quarter dots + shuffle)
        {
            const int row  = tid >> 2;
            const int part = tid & 3;
            float s = 0.0f;
            #pragma unroll
            for (int d4 = part * 32; d4 < part * 32 + 32; d4 += 4) {
                const float4 a = *(const float4*)(stage + row * SPAD + d4);
                const float4 z = *(const float4*)(Zsm + d4);
                s = fmaf(a.x, z.x, s);
                s = fmaf(a.y, z.y, s);
                s = fmaf(a.z, z.z, s);
                s = fmaf(a.w, z.w, s);
            }
            s += __shfl_xor_sync(0xffffffffu, s, 1);
            s += __shfl_xor_sync(0xffffffffu, s, 2);
            if (part == 0) den[row] = s + EPS_F;
        }

        // GEMM: 64(s) x 128(m), K = 128(d). warp: 16s x 64m -> 8 n-tiles
        float accq[8][4];
        #pragma unroll
        for (int mt = 0; mt < 8; ++mt)
            #pragma unroll
            for (int r = 0; r < 4; ++r) accq[mt][r] = 0.0f;

        #pragma unroll
        for (int kk = 0; kk < DD / 8; ++kk) {
            const int kb8 = kk * 8;
            uint32_t A[4];
            A[0] = __float_as_uint(stage[(s0 + g)     * SPAD + kb8 + t]);
            A[1] = __float_as_uint(stage[(s0 + g + 8) * SPAD + kb8 + t]);
            A[2] = __float_as_uint(stage[(s0 + g)     * SPAD + kb8 + t + 4]);
            A[3] = __float_as_uint(stage[(s0 + g + 8) * SPAD + kb8 + t + 4]);
            #pragma unroll
            for (int mt = 0; mt < 8; ++mt) {
                const int m = m0 + mt * 8 + g;
                uint32_t B[2];
                B[0] = __float_as_uint(Sdm[(kb8 + t)     * VPAD + m]);
                B[1] = __float_as_uint(Sdm[(kb8 + t + 4) * VPAD + m]);
                mma_tf32(accq[mt], A, B);
            }
        }
        __syncthreads();   // den visible; stage reads complete

        // epilogue: scale by 1/den, store
        const int r0 = chq * 64 + s0 + g;
        const float inv0 = 1.0f / den[s0 + g];
        const float inv1 = 1.0f / den[s0 + g + 8];
        #pragma unroll
        for (int mt = 0; mt < 8; ++mt) {
            const int m = m0 + mt * 8 + 2 * t;
            *(float2*)(ob + (long)r0 * DD + m) =
                make_float2(accq[mt][0] * inv0, accq[mt][1] * inv0);
            *(float2*)(ob + (long)(r0 + 8) * DD + m) =
                make_float2(accq[mt][2] * inv1, accq[mt][3] * inv1);
        }
    }
}

extern "C" void kernel_launch(void* const* d_in, const int* in_sizes, int n_in,
                              void* d_out, int out_size) {
    const float* q  = (const float*)d_in[0];
    const float* k  = (const float*)d_in[1];
    const float* v  = (const float*)d_in[2];
    const float* sc = (const float*)d_in[3];
    const float* bi = (const float*)d_in[4];
    float* out = (float*)d_out;

    cudaFuncSetAttribute(lin_attn_tc,
                         cudaFuncAttributeMaxDynamicSharedMemorySize, SMEM_BYTES);
    lin_attn_tc<<<NCTA, NT, SMEM_BYTES>>>(q, k, v, sc, bi, out);
}